// round 1
// baseline (speedup 1.0000x reference)
#include <cuda_runtime.h>
#include <math.h>

// ---------------------------------------------------------------------------
// MultiHeadAttention: B=8, S=1024, HIDDEN=1024, HEADS=16, HEAD_DIM=64
//   qkv = X @ Wqkv + b          [8192, 3072]
//   per (b,h): flash attention over 64x64 tiles
//   out = Att @ Wo + b          [8192, 1024]
// ---------------------------------------------------------------------------

#define BATCH 8
#define SEQ 1024
#define HIDDEN 1024
#define HEADS 16
#define HEAD_DIM 64
#define MTOT (BATCH * SEQ)            // 8192
#define QKV_N (3 * HIDDEN)            // 3072

// scratch (allocation-free rule: __device__ globals)
__device__ float g_qkv[MTOT * QKV_N];     // 96 MB
__device__ float g_att[MTOT * HIDDEN];    // 32 MB

// ---------------------------------------------------------------------------
// Generic 128x128 tiled SGEMM with bias: C[M,N] = A[M,K] @ B[K,N] + bias[N]
// 256 threads, 8x8 per-thread microtile, K-step 8.
// ---------------------------------------------------------------------------
template <int N, int K>
__device__ __forceinline__ void sgemm_bias_body(const float* __restrict__ A,
                                                const float* __restrict__ B,
                                                const float* __restrict__ bias,
                                                float* __restrict__ C) {
    __shared__ float As[8][128];
    __shared__ float Bs[8][128];

    const int t = threadIdx.x;
    const int bx = blockIdx.x;   // N tile
    const int by = blockIdx.y;   // M tile
    const int tx = t & 15;
    const int ty = t >> 4;

    const int arow = t >> 1;           // 0..127
    const int acol = (t & 1) * 4;      // 0 or 4
    const int brow = t >> 5;           // 0..7
    const int bcol = (t & 31) * 4;     // 0..124

    const float* Ag = A + (size_t)(by * 128 + arow) * K + acol;
    const float* Bg = B + (size_t)brow * N + bx * 128 + bcol;

    float acc[8][8];
#pragma unroll
    for (int i = 0; i < 8; i++)
#pragma unroll
        for (int j = 0; j < 8; j++) acc[i][j] = 0.f;

    for (int k0 = 0; k0 < K; k0 += 8) {
        float4 av = *(const float4*)(Ag + k0);
        float4 bv = *(const float4*)(Bg + (size_t)k0 * N);
        As[acol + 0][arow] = av.x;
        As[acol + 1][arow] = av.y;
        As[acol + 2][arow] = av.z;
        As[acol + 3][arow] = av.w;
        *(float4*)&Bs[brow][bcol] = bv;
        __syncthreads();

#pragma unroll
        for (int kk = 0; kk < 8; kk++) {
            float a[8], b[8];
            *(float4*)(a + 0) = *(const float4*)&As[kk][ty * 4];
            *(float4*)(a + 4) = *(const float4*)&As[kk][64 + ty * 4];
            *(float4*)(b + 0) = *(const float4*)&Bs[kk][tx * 4];
            *(float4*)(b + 4) = *(const float4*)&Bs[kk][64 + tx * 4];
#pragma unroll
            for (int i = 0; i < 8; i++)
#pragma unroll
                for (int j = 0; j < 8; j++) acc[i][j] += a[i] * b[j];
        }
        __syncthreads();
    }

    // epilogue: add bias, store
    float bsv[8];
#pragma unroll
    for (int jh = 0; jh < 2; jh++) {
        int n = bx * 128 + jh * 64 + tx * 4;
#pragma unroll
        for (int j = 0; j < 4; j++) bsv[jh * 4 + j] = bias[n + j];
    }
#pragma unroll
    for (int i = 0; i < 8; i++) {
        int mloc = (i < 4) ? (ty * 4 + i) : (64 + ty * 4 + (i - 4));
        size_t rowoff = (size_t)(by * 128 + mloc) * N;
#pragma unroll
        for (int jh = 0; jh < 2; jh++) {
            int n = bx * 128 + jh * 64 + tx * 4;
            float4 o;
            o.x = acc[i][jh * 4 + 0] + bsv[jh * 4 + 0];
            o.y = acc[i][jh * 4 + 1] + bsv[jh * 4 + 1];
            o.z = acc[i][jh * 4 + 2] + bsv[jh * 4 + 2];
            o.w = acc[i][jh * 4 + 3] + bsv[jh * 4 + 3];
            *(float4*)&C[rowoff + n] = o;
        }
    }
}

__global__ void __launch_bounds__(256) k_qkv_gemm(const float* __restrict__ X,
                                                  const float* __restrict__ W,
                                                  const float* __restrict__ bias) {
    sgemm_bias_body<QKV_N, HIDDEN>(X, W, bias, g_qkv);
}

__global__ void __launch_bounds__(256) k_out_gemm(const float* __restrict__ W,
                                                  const float* __restrict__ bias,
                                                  float* __restrict__ out) {
    sgemm_bias_body<HIDDEN, HIDDEN>(g_att, W, bias, out);
}

// ---------------------------------------------------------------------------
// Flash attention: grid (qtile=16, head=16, batch=8), 256 threads.
// Q tile 64x64, stream K/V in 64-row tiles with online softmax.
// Thread (tx,ty): S/O rows {4*ty+i}, cols {4*tx+j}.
// ---------------------------------------------------------------------------
__global__ void __launch_bounds__(256) k_attention() {
    __shared__ float Qs[64][64];     // q rows (pre-scaled)
    __shared__ float KVs[64][64];    // K transposed (k-major), then V (row-major)
    __shared__ float Ps[64][64];     // softmax probabilities

    const int t = threadIdx.x;
    const int qt = blockIdx.x;
    const int h = blockIdx.y;
    const int b = blockIdx.z;
    const int tx = t & 15;
    const int ty = t >> 4;

    const float scale = 0.125f;  // 1/sqrt(64)

    // --- load Q tile (scaled) ---
    {
        const int r = t >> 2;            // 0..63
        const int c0 = (t & 3) * 16;     // 0,16,32,48
        const float* src = g_qkv + (size_t)(b * SEQ + qt * 64 + r) * QKV_N + h * HEAD_DIM + c0;
#pragma unroll
        for (int i = 0; i < 4; i++) {
            float4 v = *(const float4*)(src + i * 4);
            v.x *= scale; v.y *= scale; v.z *= scale; v.w *= scale;
            *(float4*)&Qs[r][c0 + i * 4] = v;
        }
    }

    float m_i[4], l_i[4], o[4][4];
#pragma unroll
    for (int i = 0; i < 4; i++) {
        m_i[i] = -INFINITY;
        l_i[i] = 0.f;
#pragma unroll
        for (int j = 0; j < 4; j++) o[i][j] = 0.f;
    }
    __syncthreads();

    for (int kt = 0; kt < 16; kt++) {
        // --- load K tile transposed: KVs[k][token] ---
        {
            const int r = t >> 2;
            const int c0 = (t & 3) * 16;
            const float* src = g_qkv + (size_t)(b * SEQ + kt * 64 + r) * QKV_N + HIDDEN + h * HEAD_DIM + c0;
#pragma unroll
            for (int i = 0; i < 4; i++) {
                float4 v = *(const float4*)(src + i * 4);
                KVs[c0 + i * 4 + 0][r] = v.x;
                KVs[c0 + i * 4 + 1][r] = v.y;
                KVs[c0 + i * 4 + 2][r] = v.z;
                KVs[c0 + i * 4 + 3][r] = v.w;
            }
        }
        __syncthreads();

        // --- S = Q @ K^T (4x4 per thread) ---
        float s[4][4];
#pragma unroll
        for (int i = 0; i < 4; i++)
#pragma unroll
            for (int j = 0; j < 4; j++) s[i][j] = 0.f;

#pragma unroll
        for (int k = 0; k < 64; k += 4) {
            float a[4][4], bb[4][4];
#pragma unroll
            for (int i = 0; i < 4; i++)
                *(float4*)a[i] = *(const float4*)&Qs[ty * 4 + i][k];
#pragma unroll
            for (int kk = 0; kk < 4; kk++)
                *(float4*)bb[kk] = *(const float4*)&KVs[k + kk][tx * 4];
#pragma unroll
            for (int i = 0; i < 4; i++)
#pragma unroll
                for (int kk = 0; kk < 4; kk++)
#pragma unroll
                    for (int j = 0; j < 4; j++) s[i][j] += a[i][kk] * bb[kk][j];
        }

        // --- online softmax update (row reduction over 16 tx lanes) ---
#pragma unroll
        for (int i = 0; i < 4; i++) {
            float mx = fmaxf(fmaxf(s[i][0], s[i][1]), fmaxf(s[i][2], s[i][3]));
#pragma unroll
            for (int off = 1; off < 16; off <<= 1)
                mx = fmaxf(mx, __shfl_xor_sync(0xffffffffu, mx, off));
            float newm = fmaxf(m_i[i], mx);
            float corr = __expf(m_i[i] - newm);
            m_i[i] = newm;
            float rowsum = 0.f;
#pragma unroll
            for (int j = 0; j < 4; j++) {
                float p = __expf(s[i][j] - newm);
                s[i][j] = p;
                rowsum += p;
            }
#pragma unroll
            for (int off = 1; off < 16; off <<= 1)
                rowsum += __shfl_xor_sync(0xffffffffu, rowsum, off);
            l_i[i] = l_i[i] * corr + rowsum;
#pragma unroll
            for (int j = 0; j < 4; j++) o[i][j] *= corr;
        }

        // --- stage P ---
#pragma unroll
        for (int i = 0; i < 4; i++)
            *(float4*)&Ps[ty * 4 + i][tx * 4] = *(float4*)s[i];
        __syncthreads();  // P visible; everyone done reading K

        // --- load V tile (row-major, reuse KVs) ---
        {
            const int r = t >> 2;
            const int c0 = (t & 3) * 16;
            const float* src = g_qkv + (size_t)(b * SEQ + kt * 64 + r) * QKV_N + 2 * HIDDEN + h * HEAD_DIM + c0;
#pragma unroll
            for (int i = 0; i < 4; i++)
                *(float4*)&KVs[r][c0 + i * 4] = *(const float4*)(src + i * 4);
        }
        __syncthreads();

        // --- O += P @ V ---
#pragma unroll
        for (int jj = 0; jj < 64; jj += 4) {
            float p[4][4], v[4][4];
#pragma unroll
            for (int i = 0; i < 4; i++)
                *(float4*)p[i] = *(const float4*)&Ps[ty * 4 + i][jj];
#pragma unroll
            for (int kk = 0; kk < 4; kk++)
                *(float4*)v[kk] = *(const float4*)&KVs[jj + kk][tx * 4];
#pragma unroll
            for (int i = 0; i < 4; i++)
#pragma unroll
                for (int kk = 0; kk < 4; kk++)
#pragma unroll
                    for (int j = 0; j < 4; j++) o[i][j] += p[i][kk] * v[kk][j];
        }
        __syncthreads();  // before next K overwrite of KVs/Ps
    }

    // --- normalize + store ---
#pragma unroll
    for (int i = 0; i < 4; i++) {
        float inv = 1.f / l_i[i];
        float4 ov;
        ov.x = o[i][0] * inv;
        ov.y = o[i][1] * inv;
        ov.z = o[i][2] * inv;
        ov.w = o[i][3] * inv;
        size_t row = (size_t)(b * SEQ + qt * 64 + ty * 4 + i);
        *(float4*)&g_att[row * HIDDEN + h * HEAD_DIM + tx * 4] = ov;
    }
}

// ---------------------------------------------------------------------------
extern "C" void kernel_launch(void* const* d_in, const int* in_sizes, int n_in,
                              void* d_out, int out_size) {
    const float* query = (const float*)d_in[0];
    const float* w_qkv = (const float*)d_in[1];
    const float* b_qkv = (const float*)d_in[2];
    const float* w_o   = (const float*)d_in[3];
    const float* b_o   = (const float*)d_in[4];
    float* out = (float*)d_out;

    dim3 g1(QKV_N / 128, MTOT / 128);   // 24 x 64
    k_qkv_gemm<<<g1, 256>>>(query, w_qkv, b_qkv);

    dim3 g2(SEQ / 64, HEADS, BATCH);    // 16 x 16 x 8
    k_attention<<<g2, 256>>>();

    dim3 g3(HIDDEN / 128, MTOT / 128);  // 8 x 64
    k_out_gemm<<<g3, 256>>>(w_o, b_o, out);
}

// round 2
// speedup vs baseline: 2.3918x; 2.3918x over previous
#include <cuda_runtime.h>
#include <math.h>
#include <stdint.h>

// MultiHeadAttention B=8 S=1024 HIDDEN=1024 HEADS=16 HEAD_DIM=64 — tf32 tensor-core path
#define BATCH 8
#define SEQ 1024
#define HIDDEN 1024
#define HEADS 16
#define HEAD_DIM 64
#define MTOT (BATCH * SEQ)          // 8192
#define QKV_N (3 * HIDDEN)          // 3072

// scratch (__device__ globals: allocation-free rule)
__device__ float g_qkv[MTOT * QKV_N];     // 96 MB (fp32 out of GEMM1)
__device__ float g_att[MTOT * HIDDEN];    // 32 MB (tf32-rounded attention out)
__device__ float g_x [MTOT * HIDDEN];     // tf32-rounded X
__device__ float g_w1[HIDDEN * QKV_N];    // tf32-rounded Wqkv
__device__ float g_w2[HIDDEN * HIDDEN];   // tf32-rounded Wo

// ---------------------------------------------------------------------------
__device__ __forceinline__ uint32_t f2tf(float f) {
    uint32_t u; asm("cvt.rna.tf32.f32 %0, %1;" : "=r"(u) : "f"(f)); return u;
}
__device__ __forceinline__ uint32_t fbits(float f) { return __float_as_uint(f); }

__device__ __forceinline__ void mma8(float* c, uint32_t a0, uint32_t a1, uint32_t a2, uint32_t a3,
                                     uint32_t b0, uint32_t b1) {
    asm volatile(
        "mma.sync.aligned.m16n8k8.row.col.f32.tf32.tf32.f32 "
        "{%0,%1,%2,%3},{%4,%5,%6,%7},{%8,%9},{%0,%1,%2,%3};"
        : "+f"(c[0]), "+f"(c[1]), "+f"(c[2]), "+f"(c[3])
        : "r"(a0), "r"(a1), "r"(a2), "r"(a3), "r"(b0), "r"(b1));
}

__device__ __forceinline__ void cp16(uint32_t dst, const void* src) {
    asm volatile("cp.async.cg.shared.global [%0], [%1], 16;" :: "r"(dst), "l"(src));
}
__device__ __forceinline__ void cp_commit() { asm volatile("cp.async.commit_group;"); }
template <int n> __device__ __forceinline__ void cp_wait() {
    asm volatile("cp.async.wait_group %0;" :: "n"(n));
}

// ---------------------------------------------------------------------------
// prep: round fp32 -> tf32 (keeps cvt out of GEMM inner loops)
// ---------------------------------------------------------------------------
__global__ void k_round(const float* __restrict__ in, float* __restrict__ out, int n4) {
    int i = blockIdx.x * blockDim.x + threadIdx.x;
    if (i < n4) {
        float4 v = ((const float4*)in)[i];
        v.x = __uint_as_float(f2tf(v.x));
        v.y = __uint_as_float(f2tf(v.y));
        v.z = __uint_as_float(f2tf(v.z));
        v.w = __uint_as_float(f2tf(v.w));
        ((float4*)out)[i] = v;
    }
}

// ---------------------------------------------------------------------------
// tf32 GEMM: C[M,N] = A[M,K] @ B[K,N] + bias.   A,B pre-rounded to tf32.
// 128 threads (4 warps), CTA tile 128x128, BK=16, warp tile 64x64,
// double-buffered cp.async. Conflict-free pads: As stride 20, Bs stride 136.
// ---------------------------------------------------------------------------
template <int N, int K>
__global__ void __launch_bounds__(128) gemm_tf32(const float* __restrict__ A,
                                                 const float* __restrict__ B,
                                                 const float* __restrict__ bias,
                                                 float* __restrict__ C) {
    __shared__ float As[2][128][20];
    __shared__ float Bs[2][16][136];

    const int tid  = threadIdx.x;
    const int lane = tid & 31;
    const int warp = tid >> 5;
    const int bm = blockIdx.y * 128;
    const int bn = blockIdx.x * 128;
    const int wm = (warp & 1) * 64;
    const int wn = (warp >> 1) * 64;
    const int r  = lane >> 2;   // 0..7
    const int cc = lane & 3;    // 0..3

    const float* Ag = A + (size_t)(bm + tid) * K;
    const float* Bg = B + (size_t)(tid >> 3) * N + bn + (tid & 7) * 16;

    const uint32_t dstA = (uint32_t)__cvta_generic_to_shared(&As[0][tid][0]);
    const uint32_t dstB = (uint32_t)__cvta_generic_to_shared(&Bs[0][tid >> 3][(tid & 7) * 16]);
    const uint32_t bufA = (uint32_t)(sizeof(float) * 128 * 20);
    const uint32_t bufB = (uint32_t)(sizeof(float) * 16 * 136);

    float acc[4][8][4];
#pragma unroll
    for (int i = 0; i < 4; i++)
#pragma unroll
        for (int j = 0; j < 8; j++)
#pragma unroll
            for (int q = 0; q < 4; q++) acc[i][j][q] = 0.f;

    auto load_tile = [&](int buf, int kb) {
        const float* a = Ag + kb * 16;
        const float* b = Bg + (size_t)kb * 16 * N;
#pragma unroll
        for (int ch = 0; ch < 4; ch++) cp16(dstA + buf * bufA + ch * 16, a + ch * 4);
#pragma unroll
        for (int ch = 0; ch < 4; ch++) cp16(dstB + buf * bufB + ch * 16, b + ch * 4);
        cp_commit();
    };

    load_tile(0, 0);
    const int NT = K / 16;
    for (int kb = 0; kb < NT; kb++) {
        const int buf = kb & 1;
        if (kb + 1 < NT) { load_tile(buf ^ 1, kb + 1); cp_wait<1>(); }
        else             { cp_wait<0>(); }
        __syncthreads();

#pragma unroll
        for (int ks = 0; ks < 2; ks++) {
            const int k0 = ks * 8;
            uint32_t af[4][4], bf[8][2];
#pragma unroll
            for (int i = 0; i < 4; i++) {
                af[i][0] = fbits(As[buf][wm + 16 * i + r    ][k0 + cc]);
                af[i][1] = fbits(As[buf][wm + 16 * i + r + 8][k0 + cc]);
                af[i][2] = fbits(As[buf][wm + 16 * i + r    ][k0 + cc + 4]);
                af[i][3] = fbits(As[buf][wm + 16 * i + r + 8][k0 + cc + 4]);
            }
#pragma unroll
            for (int j = 0; j < 8; j++) {
                bf[j][0] = fbits(Bs[buf][k0 + cc    ][wn + 8 * j + r]);
                bf[j][1] = fbits(Bs[buf][k0 + cc + 4][wn + 8 * j + r]);
            }
#pragma unroll
            for (int i = 0; i < 4; i++)
#pragma unroll
                for (int j = 0; j < 8; j++)
                    mma8(acc[i][j], af[i][0], af[i][1], af[i][2], af[i][3], bf[j][0], bf[j][1]);
        }
        __syncthreads();
    }

    // epilogue
#pragma unroll
    for (int i = 0; i < 4; i++) {
        const int row0 = bm + wm + 16 * i + r;
#pragma unroll
        for (int j = 0; j < 8; j++) {
            const int col = bn + wn + 8 * j + 2 * cc;
            const float b0 = bias[col], b1 = bias[col + 1];
            float2 v0 = make_float2(acc[i][j][0] + b0, acc[i][j][1] + b1);
            float2 v1 = make_float2(acc[i][j][2] + b0, acc[i][j][3] + b1);
            *(float2*)&C[(size_t)row0 * N + col]       = v0;
            *(float2*)&C[(size_t)(row0 + 8) * N + col] = v1;
        }
    }
}

// ---------------------------------------------------------------------------
// Flash attention with tf32 mma. CTA: 256 threads (8 warps), q-block 128
// (16 rows/warp), K/V streamed in 64-token chunks. Q frags in registers.
// P goes D-frag -> A-frag via warp shuffles (no smem round-trip).
// Pads: Ks stride 68 (banks 4t+d), Vs stride 72 (banks 8t+d) — conflict-free.
// ---------------------------------------------------------------------------
__global__ void __launch_bounds__(256, 2) k_attention() {
    __shared__ float Ks[64][68];
    __shared__ float Vs[64][72];

    const int tid  = threadIdx.x;
    const int lane = tid & 31;
    const int warp = tid >> 5;         // 0..7
    const int qt = blockIdx.x;         // 0..7
    const int h  = blockIdx.y;
    const int b  = blockIdx.z;
    const int r  = lane >> 2;          // 0..7
    const int c  = lane & 3;           // 0..3

    // ---- Q fragments (scaled by 1/8, tf32-rounded), resident in regs ----
    uint32_t qf[8][4];
    {
        const float* Qp = g_qkv + (size_t)(b * SEQ + qt * 128 + warp * 16) * QKV_N + h * HEAD_DIM;
#pragma unroll
        for (int ks = 0; ks < 8; ks++) {
            qf[ks][0] = f2tf(Qp[(size_t)r       * QKV_N + 8 * ks + c    ] * 0.125f);
            qf[ks][1] = f2tf(Qp[(size_t)(r + 8) * QKV_N + 8 * ks + c    ] * 0.125f);
            qf[ks][2] = f2tf(Qp[(size_t)r       * QKV_N + 8 * ks + c + 4] * 0.125f);
            qf[ks][3] = f2tf(Qp[(size_t)(r + 8) * QKV_N + 8 * ks + c + 4] * 0.125f);
        }
    }

    float m0 = -INFINITY, m1 = -INFINITY, l0 = 0.f, l1 = 0.f;
    float o[8][4];
#pragma unroll
    for (int j = 0; j < 8; j++)
#pragma unroll
        for (int q = 0; q < 4; q++) o[j][q] = 0.f;

    for (int ct = 0; ct < 16; ct++) {
        // ---- cooperative load of K/V chunk (64 tokens x 64 dims), tf32-round ----
        {
            const int row = tid >> 2;            // 0..63
            const int c0  = (tid & 3) * 16;
            const float* kp = g_qkv + (size_t)(b * SEQ + ct * 64 + row) * QKV_N + HIDDEN + h * HEAD_DIM + c0;
            const float* vp = kp + HIDDEN;
#pragma unroll
            for (int i = 0; i < 4; i++) {
                float4 kv = *(const float4*)(kp + i * 4);
                Ks[row][c0 + i * 4 + 0] = __uint_as_float(f2tf(kv.x));
                Ks[row][c0 + i * 4 + 1] = __uint_as_float(f2tf(kv.y));
                Ks[row][c0 + i * 4 + 2] = __uint_as_float(f2tf(kv.z));
                Ks[row][c0 + i * 4 + 3] = __uint_as_float(f2tf(kv.w));
                float4 vv = *(const float4*)(vp + i * 4);
                Vs[row][c0 + i * 4 + 0] = __uint_as_float(f2tf(vv.x));
                Vs[row][c0 + i * 4 + 1] = __uint_as_float(f2tf(vv.y));
                Vs[row][c0 + i * 4 + 2] = __uint_as_float(f2tf(vv.z));
                Vs[row][c0 + i * 4 + 3] = __uint_as_float(f2tf(vv.w));
            }
        }
        __syncthreads();

        // ---- S = Q @ K^T : 8 token-tiles x 8 k-steps ----
        float s[8][4];
#pragma unroll
        for (int j = 0; j < 8; j++)
#pragma unroll
            for (int q = 0; q < 4; q++) s[j][q] = 0.f;

#pragma unroll
        for (int j = 0; j < 8; j++)
#pragma unroll
            for (int ks = 0; ks < 8; ks++) {
                uint32_t b0 = fbits(Ks[8 * j + r][8 * ks + c]);
                uint32_t b1 = fbits(Ks[8 * j + r][8 * ks + c + 4]);
                mma8(s[j], qf[ks][0], qf[ks][1], qf[ks][2], qf[ks][3], b0, b1);
            }

        // ---- online softmax (rows r and r+8; reduce over 4 lanes sharing row) ----
        float mx0 = -INFINITY, mx1 = -INFINITY;
#pragma unroll
        for (int j = 0; j < 8; j++) {
            mx0 = fmaxf(mx0, fmaxf(s[j][0], s[j][1]));
            mx1 = fmaxf(mx1, fmaxf(s[j][2], s[j][3]));
        }
#pragma unroll
        for (int off = 1; off < 4; off <<= 1) {
            mx0 = fmaxf(mx0, __shfl_xor_sync(0xffffffffu, mx0, off));
            mx1 = fmaxf(mx1, __shfl_xor_sync(0xffffffffu, mx1, off));
        }
        const float nm0 = fmaxf(m0, mx0), nm1 = fmaxf(m1, mx1);
        const float cor0 = __expf(m0 - nm0), cor1 = __expf(m1 - nm1);
        m0 = nm0; m1 = nm1;
        float rs0 = 0.f, rs1 = 0.f;
#pragma unroll
        for (int j = 0; j < 8; j++) {
            s[j][0] = __expf(s[j][0] - nm0);
            s[j][1] = __expf(s[j][1] - nm0);
            s[j][2] = __expf(s[j][2] - nm1);
            s[j][3] = __expf(s[j][3] - nm1);
            rs0 += s[j][0] + s[j][1];
            rs1 += s[j][2] + s[j][3];
        }
#pragma unroll
        for (int off = 1; off < 4; off <<= 1) {
            rs0 += __shfl_xor_sync(0xffffffffu, rs0, off);
            rs1 += __shfl_xor_sync(0xffffffffu, rs1, off);
        }
        l0 = l0 * cor0 + rs0;
        l1 = l1 * cor1 + rs1;
#pragma unroll
        for (int j = 0; j < 8; j++) {
            o[j][0] *= cor0; o[j][1] *= cor0;
            o[j][2] *= cor1; o[j][3] *= cor1;
        }

        // ---- O += P @ V : D-frag -> A-frag via shuffles, then mma ----
        const int sbase = lane & ~3;
        const int src1 = sbase | (c >> 1);
        const int src2 = sbase | 2 | (c >> 1);
        const bool odd = (c & 1);
#pragma unroll
        for (int kt = 0; kt < 8; kt++) {
            uint32_t p0 = f2tf(s[kt][0]), p1 = f2tf(s[kt][1]);
            uint32_t p2 = f2tf(s[kt][2]), p3 = f2tf(s[kt][3]);
            uint32_t x0 = __shfl_sync(0xffffffffu, p0, src1);
            uint32_t x1 = __shfl_sync(0xffffffffu, p1, src1);
            uint32_t x2 = __shfl_sync(0xffffffffu, p2, src1);
            uint32_t x3 = __shfl_sync(0xffffffffu, p3, src1);
            uint32_t y0 = __shfl_sync(0xffffffffu, p0, src2);
            uint32_t y1 = __shfl_sync(0xffffffffu, p1, src2);
            uint32_t y2 = __shfl_sync(0xffffffffu, p2, src2);
            uint32_t y3 = __shfl_sync(0xffffffffu, p3, src2);
            uint32_t a0 = odd ? x1 : x0;   // P[r][c]
            uint32_t a1 = odd ? x3 : x2;   // P[r+8][c]
            uint32_t a2 = odd ? y1 : y0;   // P[r][c+4]
            uint32_t a3 = odd ? y3 : y2;   // P[r+8][c+4]
#pragma unroll
            for (int j = 0; j < 8; j++) {
                uint32_t b0 = fbits(Vs[8 * kt + c    ][8 * j + r]);
                uint32_t b1 = fbits(Vs[8 * kt + c + 4][8 * j + r]);
                mma8(o[j], a0, a1, a2, a3, b0, b1);
            }
        }
        __syncthreads();
    }

    // ---- normalize, tf32-round, store (GEMM2 reads pre-rounded A) ----
    const float inv0 = 1.f / l0, inv1 = 1.f / l1;
    const size_t gq = (size_t)(b * SEQ + qt * 128 + warp * 16);
#pragma unroll
    for (int j = 0; j < 8; j++) {
        const int col = h * HEAD_DIM + 8 * j + 2 * c;
        float2 v0, v1;
        v0.x = __uint_as_float(f2tf(o[j][0] * inv0));
        v0.y = __uint_as_float(f2tf(o[j][1] * inv0));
        v1.x = __uint_as_float(f2tf(o[j][2] * inv1));
        v1.y = __uint_as_float(f2tf(o[j][3] * inv1));
        *(float2*)&g_att[(gq + r) * HIDDEN + col]     = v0;
        *(float2*)&g_att[(gq + r + 8) * HIDDEN + col] = v1;
    }
}

// ---------------------------------------------------------------------------
extern "C" void kernel_launch(void* const* d_in, const int* in_sizes, int n_in,
                              void* d_out, int out_size) {
    const float* query = (const float*)d_in[0];
    const float* w_qkv = (const float*)d_in[1];
    const float* b_qkv = (const float*)d_in[2];
    const float* w_o   = (const float*)d_in[3];
    const float* b_o   = (const float*)d_in[4];
    float* out = (float*)d_out;

    float *gx, *gw1, *gw2, *gqkv, *gatt;
    cudaGetSymbolAddress((void**)&gx,   g_x);
    cudaGetSymbolAddress((void**)&gw1,  g_w1);
    cudaGetSymbolAddress((void**)&gw2,  g_w2);
    cudaGetSymbolAddress((void**)&gqkv, g_qkv);
    cudaGetSymbolAddress((void**)&gatt, g_att);

    // 1) round inputs to tf32
    {
        int n4x = MTOT * HIDDEN / 4;
        k_round<<<(n4x + 255) / 256, 256>>>(query, gx, n4x);
        int n4w1 = HIDDEN * QKV_N / 4;
        k_round<<<(n4w1 + 255) / 256, 256>>>(w_qkv, gw1, n4w1);
        int n4w2 = HIDDEN * HIDDEN / 4;
        k_round<<<(n4w2 + 255) / 256, 256>>>(w_o, gw2, n4w2);
    }

    // 2) QKV GEMM: [8192,1024] @ [1024,3072]
    dim3 g1(QKV_N / 128, MTOT / 128);
    gemm_tf32<QKV_N, HIDDEN><<<g1, 128>>>(gx, gw1, b_qkv, gqkv);

    // 3) flash attention
    dim3 g2(SEQ / 128, HEADS, BATCH);
    k_attention<<<g2, 256>>>();

    // 4) output GEMM: [8192,1024] @ [1024,1024]
    dim3 g3(HIDDEN / 128, MTOT / 128);
    gemm_tf32<HIDDEN, HIDDEN><<<g3, 128>>>(gatt, gw2, b_o, out);
}

// round 3
// speedup vs baseline: 2.8674x; 1.1988x over previous
#include <cuda_runtime.h>
#include <math.h>
#include <stdint.h>

// MultiHeadAttention B=8 S=1024 HIDDEN=1024 HEADS=16 HEAD_DIM=64 — tf32 tensor-core path
#define BATCH 8
#define SEQ 1024
#define HIDDEN 1024
#define HEADS 16
#define HEAD_DIM 64
#define MTOT (BATCH * SEQ)          // 8192
#define QKV_N (3 * HIDDEN)          // 3072

// scratch (__device__ globals: allocation-free rule)
__device__ float g_qkv[MTOT * QKV_N];     // 96 MB (fp32 out of GEMM1)
__device__ float g_att[MTOT * HIDDEN];    // 32 MB (tf32-rounded attention out)
__device__ float g_x [MTOT * HIDDEN];     // tf32-rounded X
__device__ float g_w1[HIDDEN * QKV_N];    // tf32-rounded Wqkv
__device__ float g_w2[HIDDEN * HIDDEN];   // tf32-rounded Wo

// ---------------------------------------------------------------------------
__device__ __forceinline__ uint32_t f2tf(float f) {
    uint32_t u; asm("cvt.rna.tf32.f32 %0, %1;" : "=r"(u) : "f"(f)); return u;
}
__device__ __forceinline__ uint32_t fbits(float f) { return __float_as_uint(f); }

__device__ __forceinline__ void mma8(float* c, uint32_t a0, uint32_t a1, uint32_t a2, uint32_t a3,
                                     uint32_t b0, uint32_t b1) {
    asm volatile(
        "mma.sync.aligned.m16n8k8.row.col.f32.tf32.tf32.f32 "
        "{%0,%1,%2,%3},{%4,%5,%6,%7},{%8,%9},{%0,%1,%2,%3};"
        : "+f"(c[0]), "+f"(c[1]), "+f"(c[2]), "+f"(c[3])
        : "r"(a0), "r"(a1), "r"(a2), "r"(a3), "r"(b0), "r"(b1));
}

__device__ __forceinline__ void cp16(uint32_t dst, const void* src) {
    asm volatile("cp.async.cg.shared.global [%0], [%1], 16;" :: "r"(dst), "l"(src));
}
__device__ __forceinline__ void cp_commit() { asm volatile("cp.async.commit_group;"); }
template <int n> __device__ __forceinline__ void cp_wait() {
    asm volatile("cp.async.wait_group %0;" :: "n"(n));
}

// ---------------------------------------------------------------------------
// prep: round fp32 -> tf32
// ---------------------------------------------------------------------------
__global__ void k_round(const float* __restrict__ in, float* __restrict__ out, int n4) {
    int i = blockIdx.x * blockDim.x + threadIdx.x;
    if (i < n4) {
        float4 v = ((const float4*)in)[i];
        v.x = __uint_as_float(f2tf(v.x));
        v.y = __uint_as_float(f2tf(v.y));
        v.z = __uint_as_float(f2tf(v.z));
        v.w = __uint_as_float(f2tf(v.w));
        ((float4*)out)[i] = v;
    }
}

// ---------------------------------------------------------------------------
// tf32 GEMM: C[M,N] = A[M,K] @ B[K,N] + bias.  A,B pre-rounded to tf32.
// 256 threads (8 warps), CTA tile 128x128, BK=16, warp tile 64x32,
// 3-stage cp.async pipeline. Pads: As stride 20, Bs stride 136 (conflict-free).
// 2 CTAs/SM -> 4 warps/SMSP for latency hiding.
// ---------------------------------------------------------------------------
template <int N, int K>
__global__ void __launch_bounds__(256, 2) gemm_tf32(const float* __restrict__ A,
                                                    const float* __restrict__ B,
                                                    const float* __restrict__ bias,
                                                    float* __restrict__ C) {
    __shared__ float As[3][128][20];
    __shared__ float Bs[3][16][136];

    const int tid  = threadIdx.x;
    const int lane = tid & 31;
    const int warp = tid >> 5;             // 0..7
    const int bm = blockIdx.y * 128;
    const int bn = blockIdx.x * 128;
    const int wm = (warp & 1) * 64;        // 0,64
    const int wn = (warp >> 1) * 32;       // 0,32,64,96
    const int r  = lane >> 2;              // 0..7
    const int cc = lane & 3;               // 0..3

    // staging assignments
    const int arow = tid >> 1;             // 0..127
    const int ac0  = (tid & 1) * 8;        // 0,8
    const int brow = tid >> 4;             // 0..15
    const int bc0  = (tid & 15) * 8;       // 0..120

    const float* Ag = A + (size_t)(bm + arow) * K + ac0;
    const float* Bg = B + (size_t)brow * N + bn + bc0;

    const uint32_t sA = (uint32_t)__cvta_generic_to_shared(&As[0][arow][ac0]);
    const uint32_t sB = (uint32_t)__cvta_generic_to_shared(&Bs[0][brow][bc0]);
    const uint32_t stA = (uint32_t)(sizeof(float) * 128 * 20);
    const uint32_t stB = (uint32_t)(sizeof(float) * 16 * 136);

    float acc[4][4][4];
#pragma unroll
    for (int i = 0; i < 4; i++)
#pragma unroll
        for (int j = 0; j < 4; j++)
#pragma unroll
            for (int q = 0; q < 4; q++) acc[i][j][q] = 0.f;

    auto load_tile = [&](int st, int kb) {
        const float* a = Ag + kb * 16;
        const float* b = Bg + (size_t)kb * 16 * N;
        cp16(sA + st * stA,      a);
        cp16(sA + st * stA + 16, a + 4);
        cp16(sB + st * stB,      b);
        cp16(sB + st * stB + 16, b + 4);
        cp_commit();
    };

    const int NT = K / 16;
    load_tile(0, 0);
    load_tile(1, 1);

    for (int kb = 0; kb < NT; kb++) {
        const int st = kb % 3;
        if (kb < NT - 1) cp_wait<1>();
        else             cp_wait<0>();
        __syncthreads();
        if (kb + 2 < NT) load_tile((kb + 2) % 3, kb + 2);

#pragma unroll
        for (int ks = 0; ks < 2; ks++) {
            const int k0 = ks * 8;
            uint32_t af[4][4], bf[4][2];
#pragma unroll
            for (int i = 0; i < 4; i++) {
                af[i][0] = fbits(As[st][wm + 16 * i + r    ][k0 + cc]);
                af[i][1] = fbits(As[st][wm + 16 * i + r + 8][k0 + cc]);
                af[i][2] = fbits(As[st][wm + 16 * i + r    ][k0 + cc + 4]);
                af[i][3] = fbits(As[st][wm + 16 * i + r + 8][k0 + cc + 4]);
            }
#pragma unroll
            for (int j = 0; j < 4; j++) {
                bf[j][0] = fbits(Bs[st][k0 + cc    ][wn + 8 * j + r]);
                bf[j][1] = fbits(Bs[st][k0 + cc + 4][wn + 8 * j + r]);
            }
#pragma unroll
            for (int i = 0; i < 4; i++)
#pragma unroll
                for (int j = 0; j < 4; j++)
                    mma8(acc[i][j], af[i][0], af[i][1], af[i][2], af[i][3], bf[j][0], bf[j][1]);
        }
        __syncthreads();
    }

    // epilogue: bias + store
#pragma unroll
    for (int i = 0; i < 4; i++) {
        const int row0 = bm + wm + 16 * i + r;
#pragma unroll
        for (int j = 0; j < 4; j++) {
            const int col = bn + wn + 8 * j + 2 * cc;
            const float b0 = bias[col], b1 = bias[col + 1];
            float2 v0 = make_float2(acc[i][j][0] + b0, acc[i][j][1] + b1);
            float2 v1 = make_float2(acc[i][j][2] + b0, acc[i][j][3] + b1);
            *(float2*)&C[(size_t)row0 * N + col]       = v0;
            *(float2*)&C[(size_t)(row0 + 8) * N + col] = v1;
        }
    }
}

// ---------------------------------------------------------------------------
// Flash attention with tf32 mma (unchanged from R2).
// ---------------------------------------------------------------------------
__global__ void __launch_bounds__(256, 2) k_attention() {
    __shared__ float Ks[64][68];
    __shared__ float Vs[64][72];

    const int tid  = threadIdx.x;
    const int lane = tid & 31;
    const int warp = tid >> 5;         // 0..7
    const int qt = blockIdx.x;         // 0..7
    const int h  = blockIdx.y;
    const int b  = blockIdx.z;
    const int r  = lane >> 2;          // 0..7
    const int c  = lane & 3;           // 0..3

    uint32_t qf[8][4];
    {
        const float* Qp = g_qkv + (size_t)(b * SEQ + qt * 128 + warp * 16) * QKV_N + h * HEAD_DIM;
#pragma unroll
        for (int ks = 0; ks < 8; ks++) {
            qf[ks][0] = f2tf(Qp[(size_t)r       * QKV_N + 8 * ks + c    ] * 0.125f);
            qf[ks][1] = f2tf(Qp[(size_t)(r + 8) * QKV_N + 8 * ks + c    ] * 0.125f);
            qf[ks][2] = f2tf(Qp[(size_t)r       * QKV_N + 8 * ks + c + 4] * 0.125f);
            qf[ks][3] = f2tf(Qp[(size_t)(r + 8) * QKV_N + 8 * ks + c + 4] * 0.125f);
        }
    }

    float m0 = -INFINITY, m1 = -INFINITY, l0 = 0.f, l1 = 0.f;
    float o[8][4];
#pragma unroll
    for (int j = 0; j < 8; j++)
#pragma unroll
        for (int q = 0; q < 4; q++) o[j][q] = 0.f;

    for (int ct = 0; ct < 16; ct++) {
        {
            const int row = tid >> 2;
            const int c0  = (tid & 3) * 16;
            const float* kp = g_qkv + (size_t)(b * SEQ + ct * 64 + row) * QKV_N + HIDDEN + h * HEAD_DIM + c0;
            const float* vp = kp + HIDDEN;
#pragma unroll
            for (int i = 0; i < 4; i++) {
                float4 kv = *(const float4*)(kp + i * 4);
                Ks[row][c0 + i * 4 + 0] = __uint_as_float(f2tf(kv.x));
                Ks[row][c0 + i * 4 + 1] = __uint_as_float(f2tf(kv.y));
                Ks[row][c0 + i * 4 + 2] = __uint_as_float(f2tf(kv.z));
                Ks[row][c0 + i * 4 + 3] = __uint_as_float(f2tf(kv.w));
                float4 vv = *(const float4*)(vp + i * 4);
                Vs[row][c0 + i * 4 + 0] = __uint_as_float(f2tf(vv.x));
                Vs[row][c0 + i * 4 + 1] = __uint_as_float(f2tf(vv.y));
                Vs[row][c0 + i * 4 + 2] = __uint_as_float(f2tf(vv.z));
                Vs[row][c0 + i * 4 + 3] = __uint_as_float(f2tf(vv.w));
            }
        }
        __syncthreads();

        float s[8][4];
#pragma unroll
        for (int j = 0; j < 8; j++)
#pragma unroll
            for (int q = 0; q < 4; q++) s[j][q] = 0.f;

#pragma unroll
        for (int j = 0; j < 8; j++)
#pragma unroll
            for (int ks = 0; ks < 8; ks++) {
                uint32_t b0 = fbits(Ks[8 * j + r][8 * ks + c]);
                uint32_t b1 = fbits(Ks[8 * j + r][8 * ks + c + 4]);
                mma8(s[j], qf[ks][0], qf[ks][1], qf[ks][2], qf[ks][3], b0, b1);
            }

        float mx0 = -INFINITY, mx1 = -INFINITY;
#pragma unroll
        for (int j = 0; j < 8; j++) {
            mx0 = fmaxf(mx0, fmaxf(s[j][0], s[j][1]));
            mx1 = fmaxf(mx1, fmaxf(s[j][2], s[j][3]));
        }
#pragma unroll
        for (int off = 1; off < 4; off <<= 1) {
            mx0 = fmaxf(mx0, __shfl_xor_sync(0xffffffffu, mx0, off));
            mx1 = fmaxf(mx1, __shfl_xor_sync(0xffffffffu, mx1, off));
        }
        const float nm0 = fmaxf(m0, mx0), nm1 = fmaxf(m1, mx1);
        const float cor0 = __expf(m0 - nm0), cor1 = __expf(m1 - nm1);
        m0 = nm0; m1 = nm1;
        float rs0 = 0.f, rs1 = 0.f;
#pragma unroll
        for (int j = 0; j < 8; j++) {
            s[j][0] = __expf(s[j][0] - nm0);
            s[j][1] = __expf(s[j][1] - nm0);
            s[j][2] = __expf(s[j][2] - nm1);
            s[j][3] = __expf(s[j][3] - nm1);
            rs0 += s[j][0] + s[j][1];
            rs1 += s[j][2] + s[j][3];
        }
#pragma unroll
        for (int off = 1; off < 4; off <<= 1) {
            rs0 += __shfl_xor_sync(0xffffffffu, rs0, off);
            rs1 += __shfl_xor_sync(0xffffffffu, rs1, off);
        }
        l0 = l0 * cor0 + rs0;
        l1 = l1 * cor1 + rs1;
#pragma unroll
        for (int j = 0; j < 8; j++) {
            o[j][0] *= cor0; o[j][1] *= cor0;
            o[j][2] *= cor1; o[j][3] *= cor1;
        }

        const int sbase = lane & ~3;
        const int src1 = sbase | (c >> 1);
        const int src2 = sbase | 2 | (c >> 1);
        const bool odd = (c & 1);
#pragma unroll
        for (int kt = 0; kt < 8; kt++) {
            uint32_t p0 = f2tf(s[kt][0]), p1 = f2tf(s[kt][1]);
            uint32_t p2 = f2tf(s[kt][2]), p3 = f2tf(s[kt][3]);
            uint32_t x0 = __shfl_sync(0xffffffffu, p0, src1);
            uint32_t x1 = __shfl_sync(0xffffffffu, p1, src1);
            uint32_t x2 = __shfl_sync(0xffffffffu, p2, src1);
            uint32_t x3 = __shfl_sync(0xffffffffu, p3, src1);
            uint32_t y0 = __shfl_sync(0xffffffffu, p0, src2);
            uint32_t y1 = __shfl_sync(0xffffffffu, p1, src2);
            uint32_t y2 = __shfl_sync(0xffffffffu, p2, src2);
            uint32_t y3 = __shfl_sync(0xffffffffu, p3, src2);
            uint32_t a0 = odd ? x1 : x0;
            uint32_t a1 = odd ? x3 : x2;
            uint32_t a2 = odd ? y1 : y0;
            uint32_t a3 = odd ? y3 : y2;
#pragma unroll
            for (int j = 0; j < 8; j++) {
                uint32_t b0 = fbits(Vs[8 * kt + c    ][8 * j + r]);
                uint32_t b1 = fbits(Vs[8 * kt + c + 4][8 * j + r]);
                mma8(o[j], a0, a1, a2, a3, b0, b1);
            }
        }
        __syncthreads();
    }

    const float inv0 = 1.f / l0, inv1 = 1.f / l1;
    const size_t gq = (size_t)(b * SEQ + qt * 128 + warp * 16);
#pragma unroll
    for (int j = 0; j < 8; j++) {
        const int col = h * HEAD_DIM + 8 * j + 2 * c;
        float2 v0, v1;
        v0.x = __uint_as_float(f2tf(o[j][0] * inv0));
        v0.y = __uint_as_float(f2tf(o[j][1] * inv0));
        v1.x = __uint_as_float(f2tf(o[j][2] * inv1));
        v1.y = __uint_as_float(f2tf(o[j][3] * inv1));
        *(float2*)&g_att[(gq + r) * HIDDEN + col]     = v0;
        *(float2*)&g_att[(gq + r + 8) * HIDDEN + col] = v1;
    }
}

// ---------------------------------------------------------------------------
extern "C" void kernel_launch(void* const* d_in, const int* in_sizes, int n_in,
                              void* d_out, int out_size) {
    const float* query = (const float*)d_in[0];
    const float* w_qkv = (const float*)d_in[1];
    const float* b_qkv = (const float*)d_in[2];
    const float* w_o   = (const float*)d_in[3];
    const float* b_o   = (const float*)d_in[4];
    float* out = (float*)d_out;

    float *gx, *gw1, *gw2, *gqkv, *gatt;
    cudaGetSymbolAddress((void**)&gx,   g_x);
    cudaGetSymbolAddress((void**)&gw1,  g_w1);
    cudaGetSymbolAddress((void**)&gw2,  g_w2);
    cudaGetSymbolAddress((void**)&gqkv, g_qkv);
    cudaGetSymbolAddress((void**)&gatt, g_att);

    {
        int n4x = MTOT * HIDDEN / 4;
        k_round<<<(n4x + 255) / 256, 256>>>(query, gx, n4x);
        int n4w1 = HIDDEN * QKV_N / 4;
        k_round<<<(n4w1 + 255) / 256, 256>>>(w_qkv, gw1, n4w1);
        int n4w2 = HIDDEN * HIDDEN / 4;
        k_round<<<(n4w2 + 255) / 256, 256>>>(w_o, gw2, n4w2);
    }

    dim3 g1(QKV_N / 128, MTOT / 128);
    gemm_tf32<QKV_N, HIDDEN><<<g1, 256>>>(gx, gw1, b_qkv, gqkv);

    dim3 g2(SEQ / 128, HEADS, BATCH);
    k_attention<<<g2, 256>>>();

    dim3 g3(HIDDEN / 128, MTOT / 128);
    gemm_tf32<HIDDEN, HIDDEN><<<g3, 256>>>(gatt, gw2, b_o, out);
}

// round 8
// speedup vs baseline: 3.1334x; 1.0927x over previous
#include <cuda_runtime.h>
#include <math.h>
#include <stdint.h>

// MultiHeadAttention B=8 S=1024 HIDDEN=1024 HEADS=16 HEAD_DIM=64
// mma.sync tf32 path (tcgen05 unavailable: harness PTX target is sm_103, not sm_103a)
#define BATCH 8
#define SEQ 1024
#define HIDDEN 1024
#define HEADS 16
#define HEAD_DIM 64
#define MTOT (BATCH * SEQ)          // 8192
#define QKV_N (3 * HIDDEN)          // 3072

// scratch (__device__ globals: allocation-free rule)
__device__ float g_qkv[MTOT * QKV_N];     // 96 MB (tf32-rounded by GEMM1 epilogue)
__device__ float g_att[MTOT * HIDDEN];    // 32 MB (tf32-rounded)
__device__ float g_x  [MTOT * HIDDEN];    // tf32-rounded X
__device__ float g_w1t[QKV_N * HIDDEN];   // Wqkv^T [N,K], tf32-rounded
__device__ float g_w2t[HIDDEN * HIDDEN];  // Wo^T   [N,K], tf32-rounded

// ---------------------------------------------------------------------------
__device__ __forceinline__ uint32_t f2tf(float f) {
    uint32_t u; asm("cvt.rna.tf32.f32 %0, %1;" : "=r"(u) : "f"(f)); return u;
}
__device__ __forceinline__ uint32_t fbits(float f) { return __float_as_uint(f); }

__device__ __forceinline__ void mma8(float* c, uint32_t a0, uint32_t a1, uint32_t a2, uint32_t a3,
                                     uint32_t b0, uint32_t b1) {
    asm volatile(
        "mma.sync.aligned.m16n8k8.row.col.f32.tf32.tf32.f32 "
        "{%0,%1,%2,%3},{%4,%5,%6,%7},{%8,%9},{%0,%1,%2,%3};"
        : "+f"(c[0]), "+f"(c[1]), "+f"(c[2]), "+f"(c[3])
        : "r"(a0), "r"(a1), "r"(a2), "r"(a3), "r"(b0), "r"(b1));
}

__device__ __forceinline__ void ldsm4(uint32_t* d, uint32_t a) {
    asm volatile("ldmatrix.sync.aligned.m8n8.x4.shared.b16 {%0,%1,%2,%3}, [%4];"
                 : "=r"(d[0]), "=r"(d[1]), "=r"(d[2]), "=r"(d[3]) : "r"(a));
}
__device__ __forceinline__ void ldsm2(uint32_t* d, uint32_t a) {
    asm volatile("ldmatrix.sync.aligned.m8n8.x2.shared.b16 {%0,%1}, [%2];"
                 : "=r"(d[0]), "=r"(d[1]) : "r"(a));
}

__device__ __forceinline__ void cp16(uint32_t dst, const void* src) {
    asm volatile("cp.async.cg.shared.global [%0], [%1], 16;" :: "r"(dst), "l"(src));
}
__device__ __forceinline__ void cp_commit() { asm volatile("cp.async.commit_group;"); }
template <int n> __device__ __forceinline__ void cp_wait() {
    asm volatile("cp.async.wait_group %0;" :: "n"(n));
}
__device__ __forceinline__ uint32_t smem_u32(const void* p) {
    return (uint32_t)__cvta_generic_to_shared(p);
}

// ---------------------------------------------------------------------------
// prep kernels
// ---------------------------------------------------------------------------
__global__ void k_round(const float* __restrict__ in, float* __restrict__ out, int n4) {
    int i = blockIdx.x * blockDim.x + threadIdx.x;
    if (i < n4) {
        float4 v = ((const float4*)in)[i];
        v.x = __uint_as_float(f2tf(v.x));
        v.y = __uint_as_float(f2tf(v.y));
        v.z = __uint_as_float(f2tf(v.z));
        v.w = __uint_as_float(f2tf(v.w));
        ((float4*)out)[i] = v;
    }
}

// in[R][C] -> out[C][R], tf32-rounded.  block (32,8), grid (C/32, R/32)
__global__ void k_transpose_tf(const float* __restrict__ in, float* __restrict__ out, int R, int C) {
    __shared__ float t[32][33];
    int c = blockIdx.x * 32 + threadIdx.x;
    int r0 = blockIdx.y * 32 + threadIdx.y;
#pragma unroll
    for (int i = 0; i < 32; i += 8)
        t[threadIdx.y + i][threadIdx.x] = in[(size_t)(r0 + i) * C + c];
    __syncthreads();
    int rr = blockIdx.y * 32 + threadIdx.x;
    int cc0 = blockIdx.x * 32 + threadIdx.y;
#pragma unroll
    for (int i = 0; i < 32; i += 8)
        out[(size_t)(cc0 + i) * R + rr] = __uint_as_float(f2tf(t[threadIdx.x][threadIdx.y + i]));
}

// ---------------------------------------------------------------------------
// tf32 GEMM via mma.sync + ldmatrix: C[M,NTOT] = A[M,1024] @ Bt[N,1024]^T + bias
// CTA 128x128, BK=16, 8 warps (warp tile 64x32), 4-stage cp.async ring,
// ONE __syncthreads per k-tile. smem rows: 16 floats + 4 pad (80B) —
// conflict-free for both cp.async stores and ldmatrix 8-row phases.
// Stage layout: [A:128 rows][B:128 rows] x 80B = 20480 B; 4 stages = 80 KB.
// ROUND: tf32-round the output (GEMM1 -> feeds attention unconverted).
// ---------------------------------------------------------------------------
#define GSTG_BYTES 20480
#define GEMM_SMEM (4 * GSTG_BYTES)    // 81920

template <int NTOT, bool ROUND>
__global__ void __launch_bounds__(256, 2) gemm_tc(const float* __restrict__ A,
                                                  const float* __restrict__ Bt,
                                                  const float* __restrict__ bias,
                                                  float* __restrict__ C) {
    extern __shared__ char smem[];
    const uint32_t sb = smem_u32(smem);
    const int tid = threadIdx.x;
    const int lane = tid & 31;
    const int warp = tid >> 5;
    const int bm = blockIdx.y * 128;
    const int bn = blockIdx.x * 128;
    const int wm = (warp & 1) * 64;
    const int wn = (warp >> 1) * 32;
    const int r  = lane >> 2;
    const int cc = lane & 3;
    const int K = HIDDEN;

    // staging: thread t covers 8 floats of one A row and one B row
    const int srow = tid >> 1;
    const int scol = (tid & 1) * 8;
    const float* Ag = A  + (size_t)(bm + srow) * K + scol;
    const float* Bg = Bt + (size_t)(bn + srow) * K + scol;
    const uint32_t sA = sb + (uint32_t)srow * 80 + (uint32_t)scol * 4;
    const uint32_t sB = sA + 10240;

    auto load = [&](int kb) {
        const uint32_t o = (uint32_t)(kb & 3) * GSTG_BYTES;
        const float* a = Ag + kb * 16;
        const float* b2 = Bg + kb * 16;
        cp16(sA + o,      a);
        cp16(sA + o + 16, a + 4);
        cp16(sB + o,      b2);
        cp16(sB + o + 16, b2 + 4);
    };

    float acc[4][4][4];
#pragma unroll
    for (int i = 0; i < 4; i++)
#pragma unroll
        for (int j = 0; j < 4; j++)
#pragma unroll
            for (int q = 0; q < 4; q++) acc[i][j][q] = 0.f;

    // ldmatrix lane address offsets (bytes)
    const uint32_t aLane = (uint32_t)(wm + (lane & 15)) * 80 + (uint32_t)(lane & 16);
    const uint32_t bLane = 10240 + (uint32_t)(wn + (lane & 7)) * 80 + (uint32_t)((lane & 8) * 2);

    load(0); cp_commit();
    load(1); cp_commit();
    load(2); cp_commit();

    const int NT = K / 16;   // 64
    for (int kb = 0; kb < NT; kb++) {
        cp_wait<2>();
        __syncthreads();
        if (kb + 3 < NT) load(kb + 3);
        cp_commit();

        const uint32_t st = sb + (uint32_t)(kb & 3) * GSTG_BYTES;
        const uint32_t Ab = st + aLane;
        const uint32_t Bb = st + bLane;
#pragma unroll
        for (int ks = 0; ks < 2; ks++) {
            uint32_t af[4][4], bf[4][2];
#pragma unroll
            for (int i = 0; i < 4; i++) ldsm4(af[i], Ab + i * 1280 + ks * 32);
#pragma unroll
            for (int j = 0; j < 4; j++) ldsm2(bf[j], Bb + j * 640 + ks * 32);
#pragma unroll
            for (int i = 0; i < 4; i++)
#pragma unroll
                for (int j = 0; j < 4; j++)
                    mma8(acc[i][j], af[i][0], af[i][1], af[i][2], af[i][3], bf[j][0], bf[j][1]);
        }
    }

    // epilogue: bias (+ optional tf32 round) + store
#pragma unroll
    for (int i = 0; i < 4; i++) {
        const int row0 = bm + wm + 16 * i + r;
#pragma unroll
        for (int j = 0; j < 4; j++) {
            const int col = bn + wn + 8 * j + 2 * cc;
            const float b0 = bias[col], b1 = bias[col + 1];
            float v00 = acc[i][j][0] + b0, v01 = acc[i][j][1] + b1;
            float v10 = acc[i][j][2] + b0, v11 = acc[i][j][3] + b1;
            if (ROUND) {
                v00 = __uint_as_float(f2tf(v00));
                v01 = __uint_as_float(f2tf(v01));
                v10 = __uint_as_float(f2tf(v10));
                v11 = __uint_as_float(f2tf(v11));
            }
            *(float2*)&C[(size_t)row0 * NTOT + col]       = make_float2(v00, v01);
            *(float2*)&C[(size_t)(row0 + 8) * NTOT + col] = make_float2(v10, v11);
        }
    }
}

// ---------------------------------------------------------------------------
// Flash attention, tf32 mma.sync. 256 threads (8 warps), q-block 128,
// K/V streamed in 64-token chunks via cp.async double buffer (data already
// tf32-rounded by GEMM1 epilogue -> no conversion work here).
// smem: Kbuf[2][64][68] + Vbuf[2][64][72] = 71680 B dynamic.
// ---------------------------------------------------------------------------
#define KROW 68
#define VROW 72
#define KBUF (64 * KROW)       // floats per K buffer
#define VBUF (64 * VROW)
#define ATT_SMEM ((2 * KBUF + 2 * VBUF) * 4)   // 71680

__global__ void __launch_bounds__(256, 2) k_attention() {
    extern __shared__ float sm[];
    float* Kb = sm;                    // [2][64][KROW]
    float* Vb = sm + 2 * KBUF;         // [2][64][VROW]

    const int tid  = threadIdx.x;
    const int lane = tid & 31;
    const int warp = tid >> 5;
    const int qt = blockIdx.x;
    const int h  = blockIdx.y;
    const int b  = blockIdx.z;
    const int r  = lane >> 2;
    const int c  = lane & 3;

    // ---- Q fragments (pre-rounded tf32; x0.125 is exact) ----
    uint32_t qf[8][4];
    {
        const float* Qp = g_qkv + (size_t)(b * SEQ + qt * 128 + warp * 16) * QKV_N + h * HEAD_DIM;
#pragma unroll
        for (int ks = 0; ks < 8; ks++) {
            qf[ks][0] = fbits(Qp[(size_t)r       * QKV_N + 8 * ks + c    ] * 0.125f);
            qf[ks][1] = fbits(Qp[(size_t)(r + 8) * QKV_N + 8 * ks + c    ] * 0.125f);
            qf[ks][2] = fbits(Qp[(size_t)r       * QKV_N + 8 * ks + c + 4] * 0.125f);
            qf[ks][3] = fbits(Qp[(size_t)(r + 8) * QKV_N + 8 * ks + c + 4] * 0.125f);
        }
    }

    // cp.async staging pattern: thread -> (row, 16-float segment)
    const int srow = tid >> 2;             // 0..63
    const int sc0  = (tid & 3) * 16;       // 0,16,32,48
    const float* kbase = g_qkv + (size_t)(b * SEQ) * QKV_N + HIDDEN + h * HEAD_DIM + sc0;

    auto load_chunk = [&](int ct, int buf) {
        const float* kp = kbase + (size_t)(ct * 64 + srow) * QKV_N;
        const float* vp = kp + HIDDEN;
        const uint32_t kd = smem_u32(&Kb[buf * KBUF + srow * KROW + sc0]);
        const uint32_t vd = smem_u32(&Vb[buf * VBUF + srow * VROW + sc0]);
#pragma unroll
        for (int i = 0; i < 4; i++) cp16(kd + i * 16, kp + i * 4);
#pragma unroll
        for (int i = 0; i < 4; i++) cp16(vd + i * 16, vp + i * 4);
    };

    float m0 = -INFINITY, m1 = -INFINITY, l0 = 0.f, l1 = 0.f;
    float o[8][4];
#pragma unroll
    for (int j = 0; j < 8; j++)
#pragma unroll
        for (int q = 0; q < 4; q++) o[j][q] = 0.f;

    load_chunk(0, 0);
    cp_commit();

    for (int ct = 0; ct < 16; ct++) {
        const int buf = ct & 1;
        cp_wait<0>();
        __syncthreads();
        if (ct + 1 < 16) load_chunk(ct + 1, buf ^ 1);
        cp_commit();

        const float* Ks = &Kb[buf * KBUF];
        const float* Vs = &Vb[buf * VBUF];

        // ---- S = Q @ K^T ----
        float s[8][4];
#pragma unroll
        for (int j = 0; j < 8; j++)
#pragma unroll
            for (int q = 0; q < 4; q++) s[j][q] = 0.f;

#pragma unroll
        for (int j = 0; j < 8; j++)
#pragma unroll
            for (int ks = 0; ks < 8; ks++) {
                uint32_t b0 = fbits(Ks[(8 * j + r) * KROW + 8 * ks + c]);
                uint32_t b1 = fbits(Ks[(8 * j + r) * KROW + 8 * ks + c + 4]);
                mma8(s[j], qf[ks][0], qf[ks][1], qf[ks][2], qf[ks][3], b0, b1);
            }

        // ---- online softmax ----
        float mx0 = -INFINITY, mx1 = -INFINITY;
#pragma unroll
        for (int j = 0; j < 8; j++) {
            mx0 = fmaxf(mx0, fmaxf(s[j][0], s[j][1]));
            mx1 = fmaxf(mx1, fmaxf(s[j][2], s[j][3]));
        }
#pragma unroll
        for (int off = 1; off < 4; off <<= 1) {
            mx0 = fmaxf(mx0, __shfl_xor_sync(0xffffffffu, mx0, off));
            mx1 = fmaxf(mx1, __shfl_xor_sync(0xffffffffu, mx1, off));
        }
        const float nm0 = fmaxf(m0, mx0), nm1 = fmaxf(m1, mx1);
        const float cor0 = __expf(m0 - nm0), cor1 = __expf(m1 - nm1);
        m0 = nm0; m1 = nm1;
        float rs0 = 0.f, rs1 = 0.f;
#pragma unroll
        for (int j = 0; j < 8; j++) {
            s[j][0] = __expf(s[j][0] - nm0);
            s[j][1] = __expf(s[j][1] - nm0);
            s[j][2] = __expf(s[j][2] - nm1);
            s[j][3] = __expf(s[j][3] - nm1);
            rs0 += s[j][0] + s[j][1];
            rs1 += s[j][2] + s[j][3];
        }
#pragma unroll
        for (int off = 1; off < 4; off <<= 1) {
            rs0 += __shfl_xor_sync(0xffffffffu, rs0, off);
            rs1 += __shfl_xor_sync(0xffffffffu, rs1, off);
        }
        l0 = l0 * cor0 + rs0;
        l1 = l1 * cor1 + rs1;
#pragma unroll
        for (int j = 0; j < 8; j++) {
            o[j][0] *= cor0; o[j][1] *= cor0;
            o[j][2] *= cor1; o[j][3] *= cor1;
        }

        // ---- O += P @ V (D-frag -> A-frag via shuffles) ----
        const int sbase = lane & ~3;
        const int src1 = sbase | (c >> 1);
        const int src2 = sbase | 2 | (c >> 1);
        const bool odd = (c & 1);
#pragma unroll
        for (int kt = 0; kt < 8; kt++) {
            uint32_t p0 = f2tf(s[kt][0]), p1 = f2tf(s[kt][1]);
            uint32_t p2 = f2tf(s[kt][2]), p3 = f2tf(s[kt][3]);
            uint32_t x0 = __shfl_sync(0xffffffffu, p0, src1);
            uint32_t x1 = __shfl_sync(0xffffffffu, p1, src1);
            uint32_t x2 = __shfl_sync(0xffffffffu, p2, src1);
            uint32_t x3 = __shfl_sync(0xffffffffu, p3, src1);
            uint32_t y0 = __shfl_sync(0xffffffffu, p0, src2);
            uint32_t y1 = __shfl_sync(0xffffffffu, p1, src2);
            uint32_t y2 = __shfl_sync(0xffffffffu, p2, src2);
            uint32_t y3 = __shfl_sync(0xffffffffu, p3, src2);
            uint32_t a0 = odd ? x1 : x0;
            uint32_t a1 = odd ? x3 : x2;
            uint32_t a2 = odd ? y1 : y0;
            uint32_t a3 = odd ? y3 : y2;
#pragma unroll
            for (int j = 0; j < 8; j++) {
                uint32_t b0 = fbits(Vs[(8 * kt + c    ) * VROW + 8 * j + r]);
                uint32_t b1 = fbits(Vs[(8 * kt + c + 4) * VROW + 8 * j + r]);
                mma8(o[j], a0, a1, a2, a3, b0, b1);
            }
        }
    }

    // ---- normalize, tf32-round (feeds GEMM2), store ----
    const float inv0 = 1.f / l0, inv1 = 1.f / l1;
    const size_t gq = (size_t)(b * SEQ + qt * 128 + warp * 16);
#pragma unroll
    for (int j = 0; j < 8; j++) {
        const int col = h * HEAD_DIM + 8 * j + 2 * c;
        float2 v0, v1;
        v0.x = __uint_as_float(f2tf(o[j][0] * inv0));
        v0.y = __uint_as_float(f2tf(o[j][1] * inv0));
        v1.x = __uint_as_float(f2tf(o[j][2] * inv1));
        v1.y = __uint_as_float(f2tf(o[j][3] * inv1));
        *(float2*)&g_att[(gq + r) * HIDDEN + col]     = v0;
        *(float2*)&g_att[(gq + r + 8) * HIDDEN + col] = v1;
    }
}

// ---------------------------------------------------------------------------
extern "C" void kernel_launch(void* const* d_in, const int* in_sizes, int n_in,
                              void* d_out, int out_size) {
    const float* query = (const float*)d_in[0];
    const float* w_qkv = (const float*)d_in[1];
    const float* b_qkv = (const float*)d_in[2];
    const float* w_o   = (const float*)d_in[3];
    const float* b_o   = (const float*)d_in[4];
    float* out = (float*)d_out;

    float *gx, *gw1t, *gw2t, *gqkv, *gatt;
    cudaGetSymbolAddress((void**)&gx,   g_x);
    cudaGetSymbolAddress((void**)&gw1t, g_w1t);
    cudaGetSymbolAddress((void**)&gw2t, g_w2t);
    cudaGetSymbolAddress((void**)&gqkv, g_qkv);
    cudaGetSymbolAddress((void**)&gatt, g_att);

    cudaFuncSetAttribute(gemm_tc<QKV_N, true>,   cudaFuncAttributeMaxDynamicSharedMemorySize, GEMM_SMEM);
    cudaFuncSetAttribute(gemm_tc<HIDDEN, false>, cudaFuncAttributeMaxDynamicSharedMemorySize, GEMM_SMEM);
    cudaFuncSetAttribute(k_attention,            cudaFuncAttributeMaxDynamicSharedMemorySize, ATT_SMEM);

    // prep: round X; transpose+round weights
    {
        int n4x = MTOT * HIDDEN / 4;
        k_round<<<(n4x + 255) / 256, 256>>>(query, gx, n4x);
        dim3 tb(32, 8);
        k_transpose_tf<<<dim3(QKV_N / 32, HIDDEN / 32), tb>>>(w_qkv, gw1t, HIDDEN, QKV_N);
        k_transpose_tf<<<dim3(HIDDEN / 32, HIDDEN / 32), tb>>>(w_o, gw2t, HIDDEN, HIDDEN);
    }

    // QKV GEMM (rounds output to tf32 for attention)
    gemm_tc<QKV_N, true><<<dim3(QKV_N / 128, MTOT / 128), 256, GEMM_SMEM>>>(gx, gw1t, b_qkv, gqkv);

    // flash attention
    k_attention<<<dim3(SEQ / 128, HEADS, BATCH), 256, ATT_SMEM>>>();

    // output GEMM
    gemm_tc<HIDDEN, false><<<dim3(HIDDEN / 128, MTOT / 128), 256, GEMM_SMEM>>>(gatt, gw2t, b_o, out);
}